// round 7
// baseline (speedup 1.0000x reference)
#include <cuda_runtime.h>
#include <cuda_bf16.h>
#include <cstdint>
#include <math.h>

#define T_LEN 512
#define B_SZ  128
#define NG    768
#define WHS2  260          // Wh_s column stride (floats)
#define HS2   260          // h_s row stride (floats)
#define CLUSTER_CG 8       // col-groups per cluster (= cluster size)
#define NBG   16           // batch-groups (clusters)
#define RB    8            // rows per batch-group

// ---------------- scratch ----------------
__device__ float g_x [T_LEN * B_SZ * 256];
__device__ float g_xp[T_LEN * B_SZ * NG];

// ---------------- embedding ----------------
__global__ void embed_kernel(const int* __restrict__ tokens, const float* __restrict__ emb) {
    int gid = blockIdx.x * blockDim.x + threadIdx.x;
    int row = gid >> 6;
    int c4  = gid & 63;
    int t = row >> 7;
    int b = row & 127;
    int tok = tokens[b * T_LEN + t];
    const float4* e4 = reinterpret_cast<const float4*>(emb);
    float4*       x4 = reinterpret_cast<float4*>(g_x);
    x4[(size_t)row * 64 + c4] = e4[(size_t)tok * 64 + c4];
}

// ---------------- input projection GEMM ----------------
__global__ __launch_bounds__(256) void proj_kernel(const float* __restrict__ W,
                                                   const float* __restrict__ bias) {
    __shared__ float As[16][128];
    __shared__ float Bs[16][128];
    int m0 = blockIdx.x * 128;
    int n0 = blockIdx.y * 128;
    int tid = threadIdx.x;
    int tx = tid & 15, ty = tid >> 4;
    float acc[8][8] = {};

    for (int k0 = 0; k0 < 256; k0 += 16) {
        #pragma unroll
        for (int i = 0; i < 2; i++) {
            int fid = tid + i * 256;
            int m   = fid >> 2;
            int kv  = fid & 3;
            float4 v = *reinterpret_cast<const float4*>(
                &g_x[(size_t)(m0 + m) * 256 + k0 + kv * 4]);
            As[kv * 4 + 0][m] = v.x; As[kv * 4 + 1][m] = v.y;
            As[kv * 4 + 2][m] = v.z; As[kv * 4 + 3][m] = v.w;
        }
        #pragma unroll
        for (int i = 0; i < 2; i++) {
            int fid = tid + i * 256;
            int kr  = fid >> 5;
            int nc  = fid & 31;
            *reinterpret_cast<float4*>(&Bs[kr][nc * 4]) =
                *reinterpret_cast<const float4*>(&W[(size_t)(k0 + kr) * NG + n0 + nc * 4]);
        }
        __syncthreads();
        #pragma unroll
        for (int kk = 0; kk < 16; kk++) {
            float a[8], bf[8];
            #pragma unroll
            for (int i = 0; i < 8; i++) a[i]  = As[kk][ty * 8 + i];
            #pragma unroll
            for (int j = 0; j < 8; j++) bf[j] = Bs[kk][tx * 8 + j];
            #pragma unroll
            for (int i = 0; i < 8; i++)
                #pragma unroll
                for (int j = 0; j < 8; j++)
                    acc[i][j] = fmaf(a[i], bf[j], acc[i][j]);
        }
        __syncthreads();
    }
    #pragma unroll
    for (int i = 0; i < 8; i++) {
        size_t m = (size_t)(m0 + ty * 8 + i);
        #pragma unroll
        for (int jv = 0; jv < 2; jv++) {
            float4 o;
            int n = n0 + tx * 8 + jv * 4;
            o.x = acc[i][jv*4+0] + bias[n+0];
            o.y = acc[i][jv*4+1] + bias[n+1];
            o.z = acc[i][jv*4+2] + bias[n+2];
            o.w = acc[i][jv*4+3] + bias[n+3];
            *reinterpret_cast<float4*>(&g_xp[m * NG + n]) = o;
        }
    }
}

// ---------------- recurrent scan: clusters of 8 CTAs, DSMEM h exchange ----------------
// grid (8, 16), cluster (8,1,1): blockIdx.x = cg (32 units, = cluster rank),
// blockIdx.y = bg (8 batch rows). One cluster owns its 8 rows end-to-end:
// no global sync, no global h. h double-buffered in SMEM, pushed to the 7 peers
// via st.shared::cluster each step; one cluster barrier per step.
extern __shared__ float smem[];
__global__ __launch_bounds__(256) __cluster_dims__(CLUSTER_CG, 1, 1)
void scan_kernel(const float* __restrict__ Wh, const float* __restrict__ bh) {
    float* Wh_s  = smem;                            // [96 c'][WHS2]
    float* h_buf = smem + 96 * WHS2;                // [2][RB][HS2]
    float* red   = smem + 96 * WHS2 + 2 * RB * HS2; // [4 ks][64 pos][12]
    int cg = blockIdx.x;               // cluster rank
    int bg = blockIdx.y;
    int tid = threadIdx.x;
    int u0 = cg * 32;
    int b0 = bg * RB;
    int wid = tid >> 5;
    int lane = tid & 31;

    // GEMM-phase decode: 4 K-slices x 64 positions (4 row-pairs x 16 unit-pairs)
    int ks  = tid >> 6;
    int pos = tid & 63;
    int rp  = pos >> 4;
    int up  = pos & 15;

    // Epilogue decode: 8 rows x 32 units
    int er = tid >> 5;
    int ej = tid & 31;
    int epos = (er >> 1) * 16 + (ej >> 1);
    int esub = ((er & 1) * 2 + (ej & 1)) * 3;

    // ---- one-time Wh slice load, coalesced: warp handles (g,k) rows of 32 units ----
    // Wh_s column c' = g*32 + lo, where unit uu = 2*(lo&15) + (lo>>4).
    // Inverse: lo = (uu>>1) + ((uu&1)<<4). Lane carries uu.
    {
        int lo = (lane >> 1) + ((lane & 1) << 4);
        for (int c = wid; c < 768; c += 8) {
            int k = c & 255;
            int g = c >> 8;
            float v = Wh[(size_t)k * NG + g * 256 + u0 + lane];
            Wh_s[(g * 32 + lo) * WHS2 + k] = v;
        }
    }
    for (int i = tid; i < 2 * RB * HS2; i += 256) h_buf[i] = 0.f;

    float bhz = bh[0 * 256 + u0 + ej];
    float bhr = bh[1 * 256 + u0 + ej];
    float bhh = bh[2 * 256 + u0 + ej];

    const float4* wA[3]; const float4* wB[3];
    #pragma unroll
    for (int g = 0; g < 3; g++) {
        wA[g] = reinterpret_cast<const float4*>(&Wh_s[(g * 32 + up     ) * WHS2 + ks * 64]);
        wB[g] = reinterpret_cast<const float4*>(&Wh_s[(g * 32 + up + 16) * WHS2 + ks * 64]);
    }
    float* myred = &red[(ks * 64 + pos) * 12];

    int bglob = b0 + er;
    int u = u0 + ej;
    float hprev = 0.f;

    // prologue: xp(t=0)
    size_t xb0 = (size_t)bglob * NG;
    float xz = __ldcs(&g_xp[xb0 + u]);
    float xr = __ldcs(&g_xp[xb0 + 256 + u]);
    float xh = __ldcs(&g_xp[xb0 + 512 + u]);

    // all cluster CTAs' smem initialized before any cross-CTA push
    __syncthreads();
    asm volatile("barrier.cluster.arrive.aligned;" ::: "memory");
    asm volatile("barrier.cluster.wait.aligned;"   ::: "memory");

    for (int t = 0; t < T_LEN; t++) {
        float* h_cur  = h_buf + (t & 1) * (RB * HS2);
        float* h_next = h_buf + ((t & 1) ^ 1) * (RB * HS2);

        // prefetch xp(t+1)
        float nxz = 0.f, nxr = 0.f, nxh = 0.f;
        if (t + 1 < T_LEN) {
            size_t xb = ((size_t)(t + 1) * B_SZ + bglob) * NG;
            nxz = __ldcs(&g_xp[xb + u]);
            nxr = __ldcs(&g_xp[xb + 256 + u]);
            nxh = __ldcs(&g_xp[xb + 512 + u]);
        }

        // ---- GEMM: acc[2 rows][2 units][3 gates], K-slice of 64 ----
        const float4* h0_4 = reinterpret_cast<const float4*>(&h_cur[(rp * 2 + 0) * HS2 + ks * 64]);
        const float4* h1_4 = reinterpret_cast<const float4*>(&h_cur[(rp * 2 + 1) * HS2 + ks * 64]);
        float acc[2][2][3] = {};
        #pragma unroll 4
        for (int k4 = 0; k4 < 16; k4++) {
            float4 v0 = h0_4[k4], v1 = h1_4[k4];
            #pragma unroll
            for (int g = 0; g < 3; g++) {
                float4 a = wA[g][k4];
                float4 b = wB[g][k4];
                acc[0][0][g] = fmaf(v0.x,a.x,acc[0][0][g]); acc[0][0][g] = fmaf(v0.y,a.y,acc[0][0][g]);
                acc[0][0][g] = fmaf(v0.z,a.z,acc[0][0][g]); acc[0][0][g] = fmaf(v0.w,a.w,acc[0][0][g]);
                acc[0][1][g] = fmaf(v0.x,b.x,acc[0][1][g]); acc[0][1][g] = fmaf(v0.y,b.y,acc[0][1][g]);
                acc[0][1][g] = fmaf(v0.z,b.z,acc[0][1][g]); acc[0][1][g] = fmaf(v0.w,b.w,acc[0][1][g]);
                acc[1][0][g] = fmaf(v1.x,a.x,acc[1][0][g]); acc[1][0][g] = fmaf(v1.y,a.y,acc[1][0][g]);
                acc[1][0][g] = fmaf(v1.z,a.z,acc[1][0][g]); acc[1][0][g] = fmaf(v1.w,a.w,acc[1][0][g]);
                acc[1][1][g] = fmaf(v1.x,b.x,acc[1][1][g]); acc[1][1][g] = fmaf(v1.y,b.y,acc[1][1][g]);
                acc[1][1][g] = fmaf(v1.z,b.z,acc[1][1][g]); acc[1][1][g] = fmaf(v1.w,b.w,acc[1][1][g]);
            }
        }
        {
            float4 s0 = make_float4(acc[0][0][0], acc[0][0][1], acc[0][0][2], acc[0][1][0]);
            float4 s1 = make_float4(acc[0][1][1], acc[0][1][2], acc[1][0][0], acc[1][0][1]);
            float4 s2 = make_float4(acc[1][0][2], acc[1][1][0], acc[1][1][1], acc[1][1][2]);
            float4* r4 = reinterpret_cast<float4*>(myred);
            r4[0] = s0; r4[1] = s1; r4[2] = s2;
        }
        __syncthreads();

        // ---- epilogue: reduce 4 K-partials, nonlinearity ----
        float az = bhz, ar = bhr, ah = bhh;
        #pragma unroll
        for (int s = 0; s < 4; s++) {
            const float* rr = &red[(s * 64 + epos) * 12 + esub];
            az += rr[0]; ar += rr[1]; ah += rr[2];
        }

        float z  = __fdividef(1.f, 1.f + __expf(-(xz + az)));
        float r  = __fdividef(1.f, 1.f + __expf(-(xr + ar)));
        float e2 = __expf(2.f * (xh + r * ah));
        float hh = 1.f - __fdividef(2.f, e2 + 1.f);       // tanh
        float hn = z * hprev + (1.f - z) * hh;
        hprev = hn;

        g_x[((size_t)t * B_SZ + bglob) * 256 + u] = hn;   // next layer's input

        if (t < T_LEN - 1) {
            // stage own slice locally into h_next
            h_next[er * HS2 + u0 + ej] = hn;
            __syncthreads();

            // push own 8x32 slice (as 2x u64) to the 7 peer CTAs
            if (tid < 64) {
                int row = tid >> 3;
                int q   = tid & 3;
                int half = (tid >> 2) & 1;
                // 8 rows x 2 halves x 4 quads: each thread pushes 16B
                const float4 v = *reinterpret_cast<const float4*>(
                    &h_next[row * HS2 + u0 + (half * 4 + q) * 4]);
                unsigned long long v01, v23;
                v01 = ((unsigned long long)__float_as_uint(v.y) << 32) | __float_as_uint(v.x);
                v23 = ((unsigned long long)__float_as_uint(v.w) << 32) | __float_as_uint(v.z);
                unsigned int laddr;
                {
                    size_t a = __cvta_generic_to_shared(
                        &h_next[row * HS2 + u0 + (half * 4 + q) * 4]);
                    laddr = (unsigned int)a;
                }
                #pragma unroll
                for (int rk = 0; rk < CLUSTER_CG; rk++) {
                    if (rk == cg) continue;
                    unsigned int raddr;
                    asm volatile("mapa.shared::cluster.u32 %0, %1, %2;"
                                 : "=r"(raddr) : "r"(laddr), "r"(rk));
                    asm volatile("st.shared::cluster.u64 [%0], %1;"
                                 :: "r"(raddr), "l"(v01) : "memory");
                    asm volatile("st.shared::cluster.u64 [%0+8], %1;"
                                 :: "r"(raddr), "l"(v23) : "memory");
                }
            }
            // one cluster barrier: release own pushes, acquire peers'
            asm volatile("barrier.cluster.arrive.aligned;" ::: "memory");
            asm volatile("barrier.cluster.wait.aligned;"   ::: "memory");
        }
        xz = nxz; xr = nxr; xh = nxh;
    }
}

// ---------------- classifier head ----------------
__global__ void dense_kernel(const float* __restrict__ Wd1, const float* __restrict__ bd1,
                             const float* __restrict__ Wd2, const float* __restrict__ bd2,
                             float* __restrict__ out) {
    __shared__ float xs[256];
    __shared__ float red[256];
    int b = blockIdx.x;
    int j = threadIdx.x;
    xs[j] = g_x[((size_t)(T_LEN - 1) * B_SZ + b) * 256 + j];
    __syncthreads();
    float acc = bd1[j];
    #pragma unroll 8
    for (int k = 0; k < 256; k++) acc = fmaf(xs[k], Wd1[k * 256 + j], acc);
    float h1 = acc > 0.f ? acc : 0.f;
    red[j] = h1 * Wd2[j];
    __syncthreads();
    for (int s = 128; s > 0; s >>= 1) {
        if (j < s) red[j] += red[j + s];
        __syncthreads();
    }
    if (j == 0) out[b] = 1.f / (1.f + expf(-(red[0] + bd2[0])));
}

// ---------------- launch ----------------
extern "C" void kernel_launch(void* const* d_in, const int* in_sizes, int n_in,
                              void* d_out, int out_size) {
    const int*   tokens = (const int*)  d_in[0];
    const float* emb    = (const float*)d_in[1];
    float* out = (float*)d_out;

    const int scan_smem = (96 * WHS2 + 2 * RB * HS2 + 4 * 64 * 12) * (int)sizeof(float); // 128768 B
    cudaFuncSetAttribute(scan_kernel, cudaFuncAttributeMaxDynamicSharedMemorySize, scan_smem);

    embed_kernel<<<16384, 256>>>(tokens, emb);

    for (int l = 0; l < 4; l++) {
        const float* Wx = (const float*)d_in[2 + 4 * l];
        const float* Wh = (const float*)d_in[3 + 4 * l];
        const float* bx = (const float*)d_in[4 + 4 * l];
        const float* bh = (const float*)d_in[5 + 4 * l];

        dim3 pgrid(512, 6);
        proj_kernel<<<pgrid, 256>>>(Wx, bx);

        dim3 sgrid(CLUSTER_CG, NBG);
        scan_kernel<<<sgrid, 256, scan_smem>>>(Wh, bh);
    }

    dense_kernel<<<128, 256>>>((const float*)d_in[18], (const float*)d_in[19],
                               (const float*)d_in[20], (const float*)d_in[21], out);
}

// round 8
// speedup vs baseline: 1.5020x; 1.5020x over previous
#include <cuda_runtime.h>
#include <cuda_bf16.h>
#include <cstdint>
#include <math.h>

#define T_LEN 512
#define B_SZ  128
#define NG    768
#define TB    (T_LEN * B_SZ)      // 65536
#define WKS   260                 // weight smem row stride (floats)
#define HS2   260                 // h_s row stride (floats)
#define HSTG  9                   // h stage stride
#define BG_CTAS 32

// ---------------- scratch ----------------
__device__ float    g_x [(size_t)TB * 256];
__device__ float    g_xp[(size_t)NG * TB];     // TRANSPOSED: [n = g*256+u][t*128 + b]
__device__ float    g_h [2][B_SZ * 256];
__device__ unsigned g_bar[4 * T_LEN * 4];      // [layer][t][bg]

// f32x2 helpers
#define FMA2(acc, a, b)  asm("fma.rn.f32x2 %0, %1, %2, %0;" : "+l"(acc) : "l"(a), "l"(b))
#define PACK2(d, f)      asm("mov.b64 %0, {%1, %1};" : "=l"(d) : "f"(f))
#define UNPK2(lo, hi, v) asm("mov.b64 {%0, %1}, %2;" : "=f"(lo), "=f"(hi) : "l"(v))

// ---------------- embedding ----------------
__global__ void embed_kernel(const int* __restrict__ tokens, const float* __restrict__ emb) {
    int gid = blockIdx.x * blockDim.x + threadIdx.x;
    int row = gid >> 6;
    int c4  = gid & 63;
    int t = row >> 7;
    int b = row & 127;
    int tok = tokens[b * T_LEN + t];
    const float4* e4 = reinterpret_cast<const float4*>(emb);
    float4*       x4 = reinterpret_cast<float4*>(g_x);
    x4[(size_t)row * 64 + c4] = e4[(size_t)tok * 64 + c4];
}

// ---------------- input projection GEMM (FFMA2, transposed output) ----------------
// g_xp[n][m] = (g_x[m][:] @ W[:, n]) + bias[n],  m = t*128+b, n = g*256+u
__global__ __launch_bounds__(256) void proj_kernel(const float* __restrict__ W,
                                                   const float* __restrict__ bias) {
    __shared__ float As[16][128];
    __shared__ float Bs[16][128];
    int m0 = blockIdx.x * 128;
    int n0 = blockIdx.y * 128;
    int tid = threadIdx.x;
    int tx = tid & 15, ty = tid >> 4;

    unsigned long long acc2[8][4];   // [m-row][n-pair] f32x2 over (n even, n odd)
    #pragma unroll
    for (int i = 0; i < 8; i++)
        #pragma unroll
        for (int j = 0; j < 4; j++) acc2[i][j] = 0ull;

    for (int k0 = 0; k0 < 256; k0 += 16) {
        #pragma unroll
        for (int i = 0; i < 2; i++) {               // A tile: transposed store
            int fid = tid + i * 256;
            int m   = fid >> 2;
            int kv  = fid & 3;
            float4 v = *reinterpret_cast<const float4*>(
                &g_x[(size_t)(m0 + m) * 256 + k0 + kv * 4]);
            As[kv * 4 + 0][m] = v.x; As[kv * 4 + 1][m] = v.y;
            As[kv * 4 + 2][m] = v.z; As[kv * 4 + 3][m] = v.w;
        }
        #pragma unroll
        for (int i = 0; i < 2; i++) {               // B tile: direct copy
            int fid = tid + i * 256;
            int kr  = fid >> 5;
            int nc  = fid & 31;
            *reinterpret_cast<float4*>(&Bs[kr][nc * 4]) =
                *reinterpret_cast<const float4*>(&W[(size_t)(k0 + kr) * NG + n0 + nc * 4]);
        }
        __syncthreads();
        #pragma unroll
        for (int kk = 0; kk < 16; kk++) {
            const ulonglong2* bp = reinterpret_cast<const ulonglong2*>(&Bs[kk][tx * 8]);
            ulonglong2 bA = bp[0], bB = bp[1];      // 4 packed n-pairs
            #pragma unroll
            for (int i = 0; i < 8; i++) {
                float a = As[kk][ty * 8 + i];
                unsigned long long ad; PACK2(ad, a);
                FMA2(acc2[i][0], ad, bA.x);
                FMA2(acc2[i][1], ad, bA.y);
                FMA2(acc2[i][2], ad, bB.x);
                FMA2(acc2[i][3], ad, bB.y);
            }
        }
        __syncthreads();
    }
    // epilogue: transposed store g_xp[n][m0+ty*8 .. +7]
    #pragma unroll
    for (int j2 = 0; j2 < 4; j2++) {
        float lo[8], hi[8];
        #pragma unroll
        for (int i = 0; i < 8; i++) UNPK2(lo[i], hi[i], acc2[i][j2]);
        int nA = n0 + tx * 8 + 2 * j2;
        float bA_ = bias[nA], bB_ = bias[nA + 1];
        size_t baseA = (size_t)nA * TB + m0 + ty * 8;
        size_t baseB = baseA + TB;
        *reinterpret_cast<float4*>(&g_xp[baseA]) =
            make_float4(lo[0]+bA_, lo[1]+bA_, lo[2]+bA_, lo[3]+bA_);
        *reinterpret_cast<float4*>(&g_xp[baseA + 4]) =
            make_float4(lo[4]+bA_, lo[5]+bA_, lo[6]+bA_, lo[7]+bA_);
        *reinterpret_cast<float4*>(&g_xp[baseB]) =
            make_float4(hi[0]+bB_, hi[1]+bB_, hi[2]+bB_, hi[3]+bB_);
        *reinterpret_cast<float4*>(&g_xp[baseB + 4]) =
            make_float4(hi[4]+bB_, hi[5]+bB_, hi[6]+bB_, hi[7]+bB_);
    }
}

// ---------------- recurrent scan (R3 skeleton + warp=unit/lane=row FFMA2 GEMM) ----------------
// grid (32, 4): cg = 8 units, bg = 32 rows. Warp wid = unit u0+wid, lane = row.
// Each lane accumulates 3 gates over full K=256 in f32x2 (even/odd k halves).
// No reduction buffer; hprev stays in-register. Global barrier + g_h L2 exchange as R3.
extern __shared__ float smem[];
__global__ __launch_bounds__(256) void scan_kernel(const float* __restrict__ Wh,
                                                   const float* __restrict__ bh,
                                                   int layer) {
    float* Wg_s = smem;                           // [24][WKS], row = g*8 + w
    float* h_s  = smem + 24 * WKS;                // [32][HS2], col = global unit k
    float* h_st = smem + 24 * WKS + 32 * HS2;     // [32][HSTG]
    int cg = blockIdx.x;            // 0..31
    int bg = blockIdx.y;            // 0..3
    int tid = threadIdx.x;
    int wid = tid >> 5;             // unit index within cg
    int lane = tid & 31;            // row within bg
    int u0 = cg * 8;
    int b0 = bg * 32;
    unsigned* bar = g_bar + (layer * T_LEN) * 4 + bg;

    // one-time weight fill (8-unit coalesced chunks)
    for (int idx = tid; idx < 6144; idx += 256) {
        int w  = idx & 7;
        int gk = idx >> 3;          // 0..767
        int g  = gk >> 8;
        int k  = gk & 255;
        Wg_s[(g * 8 + w) * WKS + k] = Wh[(size_t)k * NG + g * 256 + u0 + w];
    }
    for (int i = tid; i < 32 * HS2; i += 256) h_s[i] = 0.f;

    int u = u0 + wid;
    int brow = b0 + lane;
    float bhz = bh[u], bhr = bh[256 + u], bhh = bh[512 + u];

    const ulonglong2* h2p = reinterpret_cast<const ulonglong2*>(&h_s[lane * HS2]);
    const ulonglong2* wz2 = reinterpret_cast<const ulonglong2*>(&Wg_s[(0  + wid) * WKS]);
    const ulonglong2* wr2 = reinterpret_cast<const ulonglong2*>(&Wg_s[(8  + wid) * WKS]);
    const ulonglong2* wh2 = reinterpret_cast<const ulonglong2*>(&Wg_s[(16 + wid) * WKS]);

    // xp (transposed layout): coalesced per warp
    const float* xpz = g_xp + (size_t)u * TB + brow;
    const float* xpr = xpz + (size_t)256 * TB;
    const float* xph = xpz + (size_t)512 * TB;

    float hprev = 0.f;
    float xz = __ldcs(xpz), xr = __ldcs(xpr), xh = __ldcs(xph);
    __syncthreads();

    for (int t = 0; t < T_LEN; t++) {
        // prefetch xp(t+1)
        float nxz = 0.f, nxr = 0.f, nxh = 0.f;
        if (t + 1 < T_LEN) {
            size_t off = (size_t)(t + 1) * B_SZ;
            nxz = __ldcs(xpz + off); nxr = __ldcs(xpr + off); nxh = __ldcs(xph + off);
        }

        // ---- GEMM: 3 gates x K=256, f32x2 packed over even/odd k ----
        unsigned long long az = 0ull, ag = 0ull, ah = 0ull;
        #pragma unroll 8
        for (int k4 = 0; k4 < 64; k4++) {
            ulonglong2 h2 = h2p[k4];                       // per-lane row (conflict-free)
            ulonglong2 wz = wz2[k4], wr = wr2[k4], wh = wh2[k4];  // warp-broadcast
            FMA2(az, h2.x, wz.x); FMA2(az, h2.y, wz.y);
            FMA2(ag, h2.x, wr.x); FMA2(ag, h2.y, wr.y);
            FMA2(ah, h2.x, wh.x); FMA2(ah, h2.y, wh.y);
        }
        float zl, zh_, rl, rh_, hl, hh_;
        UNPK2(zl, zh_, az); UNPK2(rl, rh_, ag); UNPK2(hl, hh_, ah);
        float azf = zl + zh_ + bhz;
        float arf = rl + rh_ + bhr;
        float ahf = hl + hh_ + bhh;

        float z  = __fdividef(1.f, 1.f + __expf(-(xz + azf)));
        float r  = __fdividef(1.f, 1.f + __expf(-(xr + arf)));
        float e2 = __expf(2.f * (xh + r * ahf));
        float cand = 1.f - __fdividef(2.f, e2 + 1.f);      // tanh
        float hn = z * hprev + (1.f - z) * cand;
        hprev = hn;

        // stage for coalesced export
        h_st[lane * HSTG + wid] = hn;
        __syncthreads();
        {
            int row = tid >> 3, j = tid & 7;
            float v = h_st[row * HSTG + j];
            int wbuf = (t & 1) ^ 1;
            __stcg(&g_h[wbuf][(b0 + row) * 256 + u0 + j], v);
            g_x[((size_t)t * B_SZ + b0 + row) * 256 + u0 + j] = v;
        }
        __syncthreads();   // all stores ordered before tid0's release

        if (t < T_LEN - 1) {
            if (tid == 0) {
                unsigned* a = &bar[t * 4];
                asm volatile("red.release.gpu.global.add.u32 [%0], %1;"
                             :: "l"(a), "r"(1u) : "memory");
                unsigned v;
                do {
                    asm volatile("ld.acquire.gpu.global.u32 %0, [%1];"
                                 : "=r"(v) : "l"(a) : "memory");
                } while (v < BG_CTAS);
            }
            __syncthreads();
            // reload full 32x256 h tile (32KB) from L2
            int wbuf = (t & 1) ^ 1;
            const float4* hg = reinterpret_cast<const float4*>(&g_h[wbuf][b0 * 256]);
            #pragma unroll
            for (int i = 0; i < 8; i++) {
                int idx = tid + i * 256;
                float4 v = __ldcg(&hg[idx]);
                int row = idx >> 6, c = idx & 63;
                *reinterpret_cast<float4*>(&h_s[row * HS2 + c * 4]) = v;
            }
            __syncthreads();
        }
        xz = nxz; xr = nxr; xh = nxh;
    }
}

// ---------------- classifier head ----------------
__global__ void dense_kernel(const float* __restrict__ Wd1, const float* __restrict__ bd1,
                             const float* __restrict__ Wd2, const float* __restrict__ bd2,
                             float* __restrict__ out) {
    __shared__ float xs[256];
    __shared__ float red[256];
    int b = blockIdx.x;
    int j = threadIdx.x;
    xs[j] = g_x[((size_t)(T_LEN - 1) * B_SZ + b) * 256 + j];
    __syncthreads();
    float acc = bd1[j];
    #pragma unroll 8
    for (int k = 0; k < 256; k++) acc = fmaf(xs[k], Wd1[k * 256 + j], acc);
    float h1 = acc > 0.f ? acc : 0.f;
    red[j] = h1 * Wd2[j];
    __syncthreads();
    for (int s = 128; s > 0; s >>= 1) {
        if (j < s) red[j] += red[j + s];
        __syncthreads();
    }
    if (j == 0) out[b] = 1.f / (1.f + expf(-(red[0] + bd2[0])));
}

// ---------------- launch ----------------
extern "C" void kernel_launch(void* const* d_in, const int* in_sizes, int n_in,
                              void* d_out, int out_size) {
    const int*   tokens = (const int*)  d_in[0];
    const float* emb    = (const float*)d_in[1];
    float* out = (float*)d_out;

    void* bar_addr; cudaGetSymbolAddress(&bar_addr, g_bar);

    const int scan_smem = (24 * WKS + 32 * HS2 + 32 * HSTG) * (int)sizeof(float); // 59392 B
    cudaFuncSetAttribute(scan_kernel, cudaFuncAttributeMaxDynamicSharedMemorySize, scan_smem);

    cudaMemsetAsync(bar_addr, 0, sizeof(unsigned) * 4 * T_LEN * 4);

    embed_kernel<<<16384, 256>>>(tokens, emb);

    for (int l = 0; l < 4; l++) {
        const float* Wx = (const float*)d_in[2 + 4 * l];
        const float* Wh = (const float*)d_in[3 + 4 * l];
        const float* bx = (const float*)d_in[4 + 4 * l];
        const float* bh = (const float*)d_in[5 + 4 * l];

        dim3 pgrid(512, 6);
        proj_kernel<<<pgrid, 256>>>(Wx, bx);

        dim3 sgrid(32, 4);
        scan_kernel<<<sgrid, 256, scan_smem>>>(Wh, bh, l);
    }

    dense_kernel<<<128, 256>>>((const float*)d_in[18], (const float*)d_in[19],
                               (const float*)d_in[20], (const float*)d_in[21], out);
}